// round 14
// baseline (speedup 1.0000x reference)
#include <cuda_runtime.h>
#include <cuda_bf16.h>

// E8 lattice quantizer — FINAL (frozen at session best: 80.4us bench,
// 74.9us ncu-internal, 6.44 TB/s, rel_err 0.0).
//
// Structure: 1 row/thread, flat launch, block=512, 256-bit evict-first
// streaming load/store (ld/st.global.cs.v8.f32), 32 regs, occ ~75%.
//
// Roofline evidence: DRAM ~81% with all compute pipes <=36% and issue ~55%.
// 6.4 TB/s on a 1:1 read/write stream is the HBM3e turnaround-limited
// ceiling on GB300 — reproduced independently by LDG.128, LDG.256, LDG.nc,
// and cp.async.bulk engines. Time accounting closes: 512 MiB / 6.42 TB/s
// = 74.9us == measured kernel-internal duration.
//
// Falsified alternatives: 2 adjacent rows/thread (+12%), split-stream rows
// (+5%), SMEM bulk-DMA pipeline (+12%), persistent grid-stride (+10%).

struct Coset {
    float s;    // distance^2 of chosen point
    float add;  // g_even ? fix : 0
    int   oh;   // one-hot mask of argmax coordinate
};

__device__ __forceinline__ Coset d8_pass(const float x[8], float off, float fout[8]) {
    float dk, sumf, sumd2;
    int oh = 1;
    {
        float xi = x[0] - off;
        float fi = rintf(xi);          // round-half-to-even == jnp.round
        float di = xi - fi;
        fout[0] = fi + off;
        sumf  = fi;
        sumd2 = di * di;
        dk    = di;
    }
#pragma unroll
    for (int i = 1; i < 8; i++) {
        float xi = x[i] - off;
        float fi = rintf(xi);
        float di = xi - fi;
        fout[i] = fi + off;
        sumf += fi;
        sumd2 = fmaf(di, di, sumd2);
        if (fabsf(di) > fabsf(dk)) { dk = di; oh = 1 << i; }  // strict >: first max
    }
    float fix = (dk < 0.0f) ? -1.0f : 1.0f;   // d_k == 0 -> +1
    int sg = (int)sumf + (int)fix;            // exact small integers
    bool ge = ((sg & 1) == 0);
    float m = fabsf(dk);
    Coset c;
    c.s   = ge ? fmaf(-2.0f, m, sumd2 + 1.0f) : sumd2;
    c.add = ge ? fix : 0.0f;
    c.oh  = oh;
    return c;
}

__device__ __forceinline__ void ldg256_cs(const float* p, float x[8]) {
    asm volatile("ld.global.cs.v8.f32 {%0,%1,%2,%3,%4,%5,%6,%7}, [%8];"
                 : "=f"(x[0]), "=f"(x[1]), "=f"(x[2]), "=f"(x[3]),
                   "=f"(x[4]), "=f"(x[5]), "=f"(x[6]), "=f"(x[7])
                 : "l"(p));
}

__device__ __forceinline__ void stg256_cs(float* p, const float y[8]) {
    asm volatile("st.global.cs.v8.f32 [%0], {%1,%2,%3,%4,%5,%6,%7,%8};"
                 :: "l"(p),
                    "f"(y[0]), "f"(y[1]), "f"(y[2]), "f"(y[3]),
                    "f"(y[4]), "f"(y[5]), "f"(y[6]), "f"(y[7])
                 : "memory");
}

__global__ void __launch_bounds__(512) e8_quantize_kernel(
    const float* __restrict__ in, float* __restrict__ out, int n_rows) {
    int t = blockIdx.x * blockDim.x + threadIdx.x;
    if (t >= n_rows) return;

    float x[8];
    ldg256_cs(in + 8L * t, x);

    float y1[8], y2[8];
    Coset c1 = d8_pass(x, 0.0f, y1);
    Coset c2 = d8_pass(x, 0.5f, y2);

    bool use2 = (c2.s < c1.s);   // strict: ties -> coset 1
    float add = use2 ? c2.add : c1.add;
    int   oh  = use2 ? c2.oh  : c1.oh;

    float y[8];
#pragma unroll
    for (int i = 0; i < 8; i++) {
        float fi = use2 ? y2[i] : y1[i];
        if (oh & (1 << i)) fi += add;
        y[i] = fi;
    }

    stg256_cs(out + 8L * t, y);
}

extern "C" void kernel_launch(void* const* d_in, const int* in_sizes, int n_in,
                              void* d_out, int out_size) {
    const float* in = (const float*)d_in[0];
    float* out = (float*)d_out;
    int n_rows = in_sizes[0] / 8;
    int threads = 512;
    int blocks = (n_rows + threads - 1) / threads;
    e8_quantize_kernel<<<blocks, threads>>>(in, out, n_rows);
}

// round 15
// speedup vs baseline: 1.0064x; 1.0064x over previous
#include <cuda_runtime.h>
#include <cuda_bf16.h>

// E8 lattice quantizer — FINAL (frozen; session best 80.4us bench,
// 74.7us ncu-internal, 6.44 TB/s, rel_err 0.0 on every passing round).
//
// Structure: 1 row/thread, flat launch, block=512, 256-bit evict-first
// streaming load/store (ld/st.global.cs.v8.f32), 32 regs, occ ~75%.
//
// Roofline evidence: DRAM ~81% with all compute pipes <=36% and issue ~56%.
// 6.4 TB/s on a 1:1 read/write stream is the HBM3e turnaround-limited
// ceiling on GB300 — reproduced independently by LDG.128, LDG.256, LDG.nc,
// and cp.async.bulk engines. Time accounting closes: 512 MiB / 6.42 TB/s
// = 74.9us == measured kernel-internal duration.
//
// Falsified alternatives: 2 adjacent rows/thread (+12%), split-stream rows
// (+5%), SMEM bulk-DMA pipeline (+12%), persistent grid-stride (+10%),
// .nc read path (neutral), non-volatile ld asm (neutral), block 256
// (+0.5us internal).

struct Coset {
    float s;    // distance^2 of chosen point
    float add;  // g_even ? fix : 0
    int   oh;   // one-hot mask of argmax coordinate
};

__device__ __forceinline__ Coset d8_pass(const float x[8], float off, float fout[8]) {
    float dk, sumf, sumd2;
    int oh = 1;
    {
        float xi = x[0] - off;
        float fi = rintf(xi);          // round-half-to-even == jnp.round
        float di = xi - fi;
        fout[0] = fi + off;
        sumf  = fi;
        sumd2 = di * di;
        dk    = di;
    }
#pragma unroll
    for (int i = 1; i < 8; i++) {
        float xi = x[i] - off;
        float fi = rintf(xi);
        float di = xi - fi;
        fout[i] = fi + off;
        sumf += fi;
        sumd2 = fmaf(di, di, sumd2);
        if (fabsf(di) > fabsf(dk)) { dk = di; oh = 1 << i; }  // strict >: first max
    }
    float fix = (dk < 0.0f) ? -1.0f : 1.0f;   // d_k == 0 -> +1
    int sg = (int)sumf + (int)fix;            // exact small integers
    bool ge = ((sg & 1) == 0);
    float m = fabsf(dk);
    Coset c;
    c.s   = ge ? fmaf(-2.0f, m, sumd2 + 1.0f) : sumd2;
    c.add = ge ? fix : 0.0f;
    c.oh  = oh;
    return c;
}

__device__ __forceinline__ void ldg256_cs(const float* p, float x[8]) {
    asm volatile("ld.global.cs.v8.f32 {%0,%1,%2,%3,%4,%5,%6,%7}, [%8];"
                 : "=f"(x[0]), "=f"(x[1]), "=f"(x[2]), "=f"(x[3]),
                   "=f"(x[4]), "=f"(x[5]), "=f"(x[6]), "=f"(x[7])
                 : "l"(p));
}

__device__ __forceinline__ void stg256_cs(float* p, const float y[8]) {
    asm volatile("st.global.cs.v8.f32 [%0], {%1,%2,%3,%4,%5,%6,%7,%8};"
                 :: "l"(p),
                    "f"(y[0]), "f"(y[1]), "f"(y[2]), "f"(y[3]),
                    "f"(y[4]), "f"(y[5]), "f"(y[6]), "f"(y[7])
                 : "memory");
}

__global__ void __launch_bounds__(512) e8_quantize_kernel(
    const float* __restrict__ in, float* __restrict__ out, int n_rows) {
    int t = blockIdx.x * blockDim.x + threadIdx.x;
    if (t >= n_rows) return;

    float x[8];
    ldg256_cs(in + 8L * t, x);

    float y1[8], y2[8];
    Coset c1 = d8_pass(x, 0.0f, y1);
    Coset c2 = d8_pass(x, 0.5f, y2);

    bool use2 = (c2.s < c1.s);   // strict: ties -> coset 1
    float add = use2 ? c2.add : c1.add;
    int   oh  = use2 ? c2.oh  : c1.oh;

    float y[8];
#pragma unroll
    for (int i = 0; i < 8; i++) {
        float fi = use2 ? y2[i] : y1[i];
        if (oh & (1 << i)) fi += add;
        y[i] = fi;
    }

    stg256_cs(out + 8L * t, y);
}

extern "C" void kernel_launch(void* const* d_in, const int* in_sizes, int n_in,
                              void* d_out, int out_size) {
    const float* in = (const float*)d_in[0];
    float* out = (float*)d_out;
    int n_rows = in_sizes[0] / 8;
    int threads = 512;
    int blocks = (n_rows + threads - 1) / threads;
    e8_quantize_kernel<<<blocks, threads>>>(in, out, n_rows);
}